// round 4
// baseline (speedup 1.0000x reference)
#include <cuda_runtime.h>
#include <cstdint>

// Problem constants
#define NTOK   65536      // T*B = 2048*32
#define D      128
#define NE     9          // experts = MULTI_INFER_NUM + 1
#define TILE   128        // tokens per CTA tile
#define NGRID  521        // upper bound on sum_e ceil(cnt[e]/TILE)
#define XPITCH 129        // padded smem row stride (bank-conflict-free)

// ---- device scratch (no allocations allowed) ----
__device__ int g_cnt[NE];
__device__ int g_base[NE];
__device__ int g_perm[NTOK];
__device__ int g_nsched;
__device__ int g_sched_e[NGRID + 8];
__device__ int g_sched_s[NGRID + 8];
__device__ int g_sched_n[NGRID + 8];
__device__ int g_any_odd;   // any odd 32-bit word nonzero => dtype is int32

// ---------------------------------------------------------------------------
__global__ void k_zero() {
    int i = threadIdx.x;
    if (i < NE) g_cnt[i] = 0;
    if (i == NE) g_any_odd = 0;
}

// Dtype probe. positions is either int32[65536] (256KB) or int64[65536] (512KB).
// We read ONLY the first 65536 32-bit words (256KB) — in-bounds for both.
// int64 with values 0..15  -> odd words (high halves) are ALL zero.
// int32 with values 0..15  -> odd words are other positions, mostly nonzero.
__global__ void k_detect(const unsigned int* __restrict__ p) {
    int i = blockIdx.x * blockDim.x + threadIdx.x;   // 0..32767
    if (i < NTOK / 2) {
        if (p[2 * i + 1] != 0u) g_any_odd = 1;       // benign race, monotone
    }
}

__device__ __forceinline__ int expert_of(const void* pos, int i) {
    long long v;
    if (g_any_odd == 0) v = ((const long long*)pos)[i];   // int64
    else                v = (long long)(((const int*)pos)[i]);  // int32
    if (v < 0) v = 0;
    return (v < 8) ? (int)v : 8;
}

__global__ void k_count(const void* __restrict__ pos) {
    int i = blockIdx.x * blockDim.x + threadIdx.x;
    if (i < NTOK) atomicAdd(&g_cnt[expert_of(pos, i)], 1);
}

__global__ void k_sched() {
    if (threadIdx.x == 0 && blockIdx.x == 0) {
        int off = 0, ns = 0;
        for (int e = 0; e < NE; e++) {
            g_base[e] = off;
            int c = g_cnt[e];
            for (int s = 0; s < c; s += TILE) {
                g_sched_e[ns] = e;
                g_sched_s[ns] = off + s;
                g_sched_n[ns] = (c - s < TILE) ? (c - s) : TILE;
                ns++;
            }
            off += c;
        }
        g_nsched = ns;
    }
}

__global__ void k_scatter(const void* __restrict__ pos) {
    int i = blockIdx.x * blockDim.x + threadIdx.x;
    if (i < NTOK) {
        int e = expert_of(pos, i);
        int slot = atomicAdd(&g_base[e], 1);
        g_perm[slot] = i;
    }
}

// ---------------------------------------------------------------------------
// Packed f32x2 helpers (Blackwell)
__device__ __forceinline__ unsigned long long pack2(float v) {
    unsigned long long r;
    asm("mov.b64 %0, {%1, %1};" : "=l"(r) : "r"(__float_as_uint(v)));
    return r;
}
__device__ __forceinline__ void unpack2(unsigned long long v, float& lo, float& hi) {
    unsigned int a, b;
    asm("mov.b64 {%0, %1}, %2;" : "=r"(a), "=r"(b) : "l"(v));
    lo = __uint_as_float(a);
    hi = __uint_as_float(b);
}

__device__ __forceinline__ float fsig(float x) {
    return __fdividef(1.0f, 1.0f + __expf(-x));
}
__device__ __forceinline__ float ftnh(float x) {
    return __fdividef(2.0f, 1.0f + __expf(-2.0f * x)) - 1.0f;
}

// ---------------------------------------------------------------------------
// Fused main kernel: one CTA = 128 tokens of one expert, both layers.
// smem: X0[128][129] + X1[128][129] + Wsm[4][128][32]  (fp32)
#define SMEM_FLOATS (2 * 128 * XPITCH + 4 * 128 * 32)
#define SMEM_BYTES  (SMEM_FLOATS * 4)

extern "C" __global__ void __launch_bounds__(256, 1)
k_main(const float* __restrict__ Xg, const float* __restrict__ Ws,
       const float* __restrict__ Bs, float* __restrict__ Out)
{
    int sid = blockIdx.x;
    if (sid >= g_nsched) return;
    const int e   = g_sched_e[sid];
    const int s0  = g_sched_s[sid];
    const int len = g_sched_n[sid];

    extern __shared__ float sm[];
    float* X0  = sm;                      // 128*129
    float* X1  = X0 + 128 * XPITCH;       // 128*129
    float* Wsm = X1 + 128 * XPITCH;       // 4*128*32, layout [m][k][f]
    __shared__ int idx[TILE];

    const int tid = threadIdx.x;
    if (tid < TILE) idx[tid] = (tid < len) ? g_perm[s0 + tid] : -1;
    __syncthreads();

    // Gather X tile into smem (zero-pad unused rows)
    #pragma unroll 4
    for (int i = 0; i < 64; i++) {
        int el  = tid + i * 256;
        int row = el >> 7, col = el & 127;
        int t = idx[row];
        X0[row * XPITCH + col] = (t >= 0) ? Xg[t * D + col] : 0.0f;
    }

    const int ty = tid >> 4;   // 0..15 -> row block of 8
    const int tx = tid & 15;   // 0..15 -> col pair

    for (int l = 0; l < 2; l++) {
        float* Xc = (l == 0) ? X0 : X1;
        const float* Wb = Ws + (size_t)l * 4 * NE * D * D + (size_t)e * D * D;
        const float* Bb = Bs + (size_t)l * 4 * NE * D + (size_t)e * D;

        for (int fc = 0; fc < 4; fc++) {
            const int f0 = fc * 32;
            __syncthreads();  // Wsm reuse hazard + X1 write->read across layers

            // Stage W chunk: 4 mats x 128(k) x 32(f)
            #pragma unroll 4
            for (int i = 0; i < 64; i++) {
                int el = tid + i * 256;
                int m  = el >> 12;
                int r  = el & 4095;
                int k  = r >> 5, f = r & 31;
                Wsm[el] = Wb[(size_t)m * NE * D * D + k * D + f0 + f];
            }
            __syncthreads();

            // 4 simultaneous 128x32 matmuls over K=128, packed f32x2
            unsigned long long acc[4][8];
            #pragma unroll
            for (int m = 0; m < 4; m++)
                #pragma unroll
                for (int r = 0; r < 8; r++) acc[m][r] = 0ull;

            #pragma unroll 2
            for (int k = 0; k < 128; k++) {
                unsigned long long xa2[8];
                #pragma unroll
                for (int r = 0; r < 8; r++)
                    xa2[r] = pack2(Xc[(ty * 8 + r) * XPITCH + k]);
                #pragma unroll
                for (int m = 0; m < 4; m++) {
                    unsigned long long wv =
                        *(const unsigned long long*)(Wsm + m * 4096 + k * 32 + (tx << 1));
                    #pragma unroll
                    for (int r = 0; r < 8; r++)
                        asm("fma.rn.f32x2 %0, %1, %2, %0;"
                            : "+l"(acc[m][r]) : "l"(xa2[r]), "l"(wv));
                }
            }

            // Biases for this thread's 2 output columns, all 4 mats
            float2 bb[4];
            #pragma unroll
            for (int m = 0; m < 4; m++)
                bb[m] = *(const float2*)(Bb + (size_t)m * NE * D + f0 + (tx << 1));

            // Gating epilogue
            #pragma unroll
            for (int r = 0; r < 8; r++) {
                int row = ty * 8 + r;
                float sf0, sf1, lg0, lg1, lf0, lf1, of0, of1;
                unpack2(acc[0][r], sf0, sf1);
                unpack2(acc[1][r], lg0, lg1);
                unpack2(acc[2][r], lf0, lf1);
                unpack2(acc[3][r], of0, of1);
                sf0 += bb[0].x; sf1 += bb[0].y;
                lg0 += bb[1].x; lg1 += bb[1].y;
                lf0 += bb[2].x; lf1 += bb[2].y;
                of0 += bb[3].x; of1 += bb[3].y;

                int cbase = f0 + (tx << 1);
                float x0 = Xc[row * XPITCH + cbase];
                float x1 = Xc[row * XPITCH + cbase + 1];

                float nr0 = x0 * fsig(sf0) + ftnh(lg0) * fsig(lf0);
                float nr1 = x1 * fsig(sf1) + ftnh(lg1) * fsig(lf1);
                float o0 = ftnh(nr0) * fsig(of0);
                float o1 = ftnh(nr1) * fsig(of1);

                if (l == 0) {
                    X1[row * XPITCH + cbase]     = o0;
                    X1[row * XPITCH + cbase + 1] = o1;
                } else {
                    int t = idx[row];
                    if (t >= 0) {
                        float2 v; v.x = o0; v.y = o1;
                        *(float2*)(Out + (size_t)t * D + cbase) = v;
                    }
                }
            }
        }
    }
}

// ---------------------------------------------------------------------------
extern "C" void kernel_launch(void* const* d_in, const int* in_sizes, int n_in,
                              void* d_out, int out_size)
{
    const void*  pos = d_in[0];                       // positions  [T,B] int32/int64
    const float* X   = (const float*)d_in[1];         // outputs    [T,B,128] f32
    const float* Ws  = (const float*)d_in[2];         // [2,4,9,128,128] f32
    const float* Bs  = (const float*)d_in[3];         // [2,4,9,128] f32
    float* Out = (float*)d_out;

    // idempotent; safe to call every time (not a stream op, not an allocation)
    cudaFuncSetAttribute(k_main, cudaFuncAttributeMaxDynamicSharedMemorySize,
                         SMEM_BYTES);
    (void)in_sizes; (void)n_in; (void)out_size;

    k_zero<<<1, 32>>>();
    k_detect<<<128, 256>>>((const unsigned int*)pos);
    k_count<<<NTOK / 256, 256>>>(pos);
    k_sched<<<1, 32>>>();
    k_scatter<<<NTOK / 256, 256>>>(pos);
    k_main<<<NGRID, 256, SMEM_BYTES>>>(X, Ws, Bs, Out);
}

// round 11
// speedup vs baseline: 2.0423x; 2.0423x over previous
#include <cuda_runtime.h>
#include <cuda_bf16.h>
#include <cstdint>

#define NTOK   65536
#define D      128
#define NE     9
#define TILE   128
#define NGRID  521
#define XP     132          // smem X pitch in floats

// ---------------- device scratch ----------------
__device__ int g_cnt[NE];
__device__ int g_base[NE];
__device__ int g_perm[NTOK];
__device__ int g_nsched;
__device__ int g_sched_e[NGRID + 8];
__device__ int g_sched_s[NGRID + 8];
__device__ int g_sched_n[NGRID + 8];
__device__ int g_any_odd;

// W fragments pre-arranged for mma.sync B operand:
// index = (((me*9 + e)*16 + nt)*8 + ks)*32 + lane,  me = l*4+m (0..7)
// uint4 = { b0_hi, b1_hi, b0_lo, b1_lo }
#define WF_MAT_STRIDE (9 * 16 * 8 * 32)
__device__ __align__(16) uint4 g_wf[8 * WF_MAT_STRIDE];

// ---------------- helpers ----------------
__device__ __forceinline__ uint32_t pack_bf(float a, float b) {
    __nv_bfloat162 h = __floats2bfloat162_rn(a, b);   // .x = a (low), .y = b (high)
    return *(uint32_t*)&h;
}
__device__ __forceinline__ float fsig(float x) {
    return __fdividef(1.0f, 1.0f + __expf(-x));
}
__device__ __forceinline__ float ftnh(float x) {
    return __fdividef(2.0f, 1.0f + __expf(-2.0f * x)) - 1.0f;
}
__device__ __forceinline__ float gate(float x, float sf, float lg, float lf, float of) {
    float nr = x * fsig(sf) + ftnh(lg) * fsig(lf);
    return ftnh(nr) * fsig(of);
}

#define MMA(c, a, b0_, b1_)                                               \
    asm volatile(                                                         \
        "mma.sync.aligned.m16n8k16.row.col.f32.bf16.bf16.f32 "            \
        "{%0,%1,%2,%3}, {%4,%5,%6,%7}, {%8,%9}, {%0,%1,%2,%3};"           \
        : "+f"(c[0]), "+f"(c[1]), "+f"(c[2]), "+f"(c[3])                  \
        : "r"(a[0]), "r"(a[1]), "r"(a[2]), "r"(a[3]), "r"(b0_), "r"(b1_))

// ---------------- preprocessing kernels ----------------
__global__ void k_zero() {
    int i = threadIdx.x;
    if (i < NE) g_cnt[i] = 0;
    if (i == NE) g_any_odd = 0;
}
__global__ void k_detect(const unsigned int* __restrict__ p) {
    int i = blockIdx.x * blockDim.x + threadIdx.x;
    if (i < NTOK / 2) {
        if (p[2 * i + 1] != 0u) g_any_odd = 1;   // int32 detected
    }
}
__device__ __forceinline__ int expert_of(const void* pos, int i) {
    long long v;
    if (g_any_odd == 0) v = ((const long long*)pos)[i];
    else                v = (long long)(((const int*)pos)[i]);
    if (v < 0) v = 0;
    return (v < 8) ? (int)v : 8;
}
__global__ void k_count(const void* __restrict__ pos) {
    int i = blockIdx.x * blockDim.x + threadIdx.x;
    if (i < NTOK) atomicAdd(&g_cnt[expert_of(pos, i)], 1);
}
__global__ void k_sched2() {
    __shared__ int sb[NE], sc[NE], tb[NE + 1];
    int tid = threadIdx.x;
    if (tid == 0) {
        int off = 0, t = 0;
        for (int e = 0; e < NE; e++) {
            sb[e] = off; sc[e] = g_cnt[e]; tb[e] = t;
            g_base[e] = off;
            off += sc[e];
            t += (sc[e] + TILE - 1) / TILE;
        }
        tb[NE] = t;
        g_nsched = t;
    }
    __syncthreads();
    int i = tid;
    if (i < tb[NE]) {
        int e = 0;
        while (tb[e + 1] <= i) e++;
        int k = i - tb[e];
        g_sched_e[i] = e;
        g_sched_s[i] = sb[e] + k * TILE;
        int rem = sc[e] - k * TILE;
        g_sched_n[i] = rem < TILE ? rem : TILE;
    }
}
__global__ void k_scatter(const void* __restrict__ pos) {
    int i = blockIdx.x * blockDim.x + threadIdx.x;
    if (i < NTOK) {
        int e = expert_of(pos, i);
        int slot = atomicAdd(&g_base[e], 1);
        g_perm[slot] = i;
    }
}
// Bake W into per-lane B fragments (hi/lo split). One thread per fragment slot.
__global__ void k_prep_w(const float* __restrict__ Ws) {
    int gid = blockIdx.x * 256 + threadIdx.x;     // 294912 total
    int lane = gid & 31;
    int ks   = (gid >> 5) & 7;
    int nt   = (gid >> 8) & 15;
    int rest = gid >> 12;                          // 0..71
    int e    = rest % NE;
    int me   = rest / NE;

    int k0 = ks * 16 + (lane & 3) * 2;
    int n  = nt * 8 + (lane >> 2);
    const float* Wm = Ws + ((size_t)me * NE + e) * 16384;   // [d][f]
    float w00 = Wm[(size_t)k0 * 128 + n];
    float w01 = Wm[(size_t)(k0 + 1) * 128 + n];
    float w10 = Wm[(size_t)(k0 + 8) * 128 + n];
    float w11 = Wm[(size_t)(k0 + 9) * 128 + n];

    float h00 = __bfloat162float(__float2bfloat16(w00));
    float h01 = __bfloat162float(__float2bfloat16(w01));
    float h10 = __bfloat162float(__float2bfloat16(w10));
    float h11 = __bfloat162float(__float2bfloat16(w11));

    uint4 v;
    v.x = pack_bf(h00, h01);
    v.y = pack_bf(h10, h11);
    v.z = pack_bf(w00 - h00, w01 - h01);
    v.w = pack_bf(w10 - h10, w11 - h11);
    g_wf[gid] = v;
}

// ---------------- main fused kernel ----------------
#define SMEM_FLOATS (128 * XP + 1024 + 128)
#define SMEM_BYTES  (SMEM_FLOATS * 4)

extern "C" __global__ void __launch_bounds__(256)
k_main(const float* __restrict__ Xg, const float* __restrict__ Bs,
       float* __restrict__ Out)
{
    int sid = blockIdx.x;
    if (sid >= g_nsched) return;
    const int e   = g_sched_e[sid];
    const int s0  = g_sched_s[sid];
    const int len = g_sched_n[sid];

    extern __shared__ float sm[];
    float* Xs   = sm;                 // [128][XP]
    float* sb   = Xs + 128 * XP;      // [8][128] biases (2 layers x 4 mats)
    int*   sidx = (int*)(sb + 1024);  // [128]

    const int tid = threadIdx.x, warp = tid >> 5, lane = tid & 31;

    if (tid < TILE) sidx[tid] = (tid < len) ? g_perm[s0 + tid] : -1;
    #pragma unroll
    for (int i = tid; i < 1024; i += 256) {
        int lm = i >> 7, f = i & 127;
        sb[i] = Bs[((size_t)lm * NE + e) * 128 + f];
    }
    __syncthreads();

    // Gather X tile (fp32) into smem
    {
        const float4* X4 = (const float4*)Xg;
        #pragma unroll 4
        for (int i = 0; i < 16; i++) {
            int el = tid + i * 256;          // 4096 float4s
            int row = el >> 5, c4 = el & 31;
            int t = sidx[row];
            float4 v = make_float4(0.f, 0.f, 0.f, 0.f);
            if (t >= 0) v = X4[(size_t)t * 32 + c4];
            *(float4*)&Xs[row * XP + c4 * 4] = v;
        }
    }
    __syncthreads();

    const int g  = lane >> 2;        // 0..7
    const int t4 = lane & 3;         // 0..3
    const int r_lo = warp * 16 + g;
    const int r_hi = r_lo + 8;

    for (int l = 0; l < 2; l++) {
        // ---- build A fragments (hi/lo) for this warp's 16 rows, K=128 ----
        uint32_t ahi[8][4], alo[8][4];
        #pragma unroll
        for (int ks = 0; ks < 8; ks++) {
            int c0 = ks * 16 + t4 * 2, c8 = c0 + 8;
            float2 v00 = *(float2*)&Xs[r_lo * XP + c0];
            float2 v10 = *(float2*)&Xs[r_hi * XP + c0];
            float2 v01 = *(float2*)&Xs[r_lo * XP + c8];
            float2 v11 = *(float2*)&Xs[r_hi * XP + c8];
            float h;
            h = __bfloat162float(__float2bfloat16(v00.x));
            float h2 = __bfloat162float(__float2bfloat16(v00.y));
            ahi[ks][0] = pack_bf(h, h2);  alo[ks][0] = pack_bf(v00.x - h, v00.y - h2);
            h = __bfloat162float(__float2bfloat16(v10.x));
            h2 = __bfloat162float(__float2bfloat16(v10.y));
            ahi[ks][1] = pack_bf(h, h2);  alo[ks][1] = pack_bf(v10.x - h, v10.y - h2);
            h = __bfloat162float(__float2bfloat16(v01.x));
            h2 = __bfloat162float(__float2bfloat16(v01.y));
            ahi[ks][2] = pack_bf(h, h2);  alo[ks][2] = pack_bf(v01.x - h, v01.y - h2);
            h = __bfloat162float(__float2bfloat16(v11.x));
            h2 = __bfloat162float(__float2bfloat16(v11.y));
            ahi[ks][3] = pack_bf(h, h2);  alo[ks][3] = pack_bf(v11.x - h, v11.y - h2);
        }

        const float* sbl = sb + l * 512;

        for (int nt = 0; nt < 16; nt++) {
            float acc[4][4];
            #pragma unroll
            for (int m = 0; m < 4; m++)
                #pragma unroll
                for (int q = 0; q < 4; q++) acc[m][q] = 0.f;

            const uint4* wp = g_wf +
                ((((size_t)(l * 4) * NE + e) * 16 + nt) * 8) * 32 + lane;

            #pragma unroll
            for (int ks = 0; ks < 8; ks++) {
                uint4 w0 = wp[0 * WF_MAT_STRIDE + ks * 32];
                uint4 w1 = wp[1 * WF_MAT_STRIDE + ks * 32];
                uint4 w2 = wp[2 * WF_MAT_STRIDE + ks * 32];
                uint4 w3 = wp[3 * WF_MAT_STRIDE + ks * 32];
                // hi * hi
                MMA(acc[0], ahi[ks], w0.x, w0.y);
                MMA(acc[1], ahi[ks], w1.x, w1.y);
                MMA(acc[2], ahi[ks], w2.x, w2.y);
                MMA(acc[3], ahi[ks], w3.x, w3.y);
                // hi * lo
                MMA(acc[0], ahi[ks], w0.z, w0.w);
                MMA(acc[1], ahi[ks], w1.z, w1.w);
                MMA(acc[2], ahi[ks], w2.z, w2.w);
                MMA(acc[3], ahi[ks], w3.z, w3.w);
                // lo * hi
                MMA(acc[0], alo[ks], w0.x, w0.y);
                MMA(acc[1], alo[ks], w1.x, w1.y);
                MMA(acc[2], alo[ks], w2.x, w2.y);
                MMA(acc[3], alo[ks], w3.x, w3.y);
            }

            // ---- epilogue for this 16x8 tile ----
            const int c0 = nt * 8 + t4 * 2;
            float2 xlo = *(float2*)&Xs[r_lo * XP + c0];
            float2 xhi = *(float2*)&Xs[r_hi * XP + c0];
            float2 b0 = *(float2*)&sbl[0 * 128 + c0];
            float2 b1 = *(float2*)&sbl[1 * 128 + c0];
            float2 b2 = *(float2*)&sbl[2 * 128 + c0];
            float2 b3 = *(float2*)&sbl[3 * 128 + c0];

            float o0 = gate(xlo.x, acc[0][0] + b0.x, acc[1][0] + b1.x,
                            acc[2][0] + b2.x, acc[3][0] + b3.x);
            float o1 = gate(xlo.y, acc[0][1] + b0.y, acc[1][1] + b1.y,
                            acc[2][1] + b2.y, acc[3][1] + b3.y);
            float o2 = gate(xhi.x, acc[0][2] + b0.x, acc[1][2] + b1.x,
                            acc[2][2] + b2.x, acc[3][2] + b3.x);
            float o3 = gate(xhi.y, acc[0][3] + b0.y, acc[1][3] + b1.y,
                            acc[2][3] + b2.y, acc[3][3] + b3.y);

            if (l == 0) {
                *(float2*)&Xs[r_lo * XP + c0] = make_float2(o0, o1);
                *(float2*)&Xs[r_hi * XP + c0] = make_float2(o2, o3);
            } else {
                int tl = sidx[r_lo];
                if (tl >= 0)
                    *(float2*)&Out[(size_t)tl * D + c0] = make_float2(o0, o1);
                int th = sidx[r_hi];
                if (th >= 0)
                    *(float2*)&Out[(size_t)th * D + c0] = make_float2(o2, o3);
            }
        }
        if (l == 0) __syncwarp();   // warp-private rows: warp sync suffices
    }
}

// ---------------- launch ----------------
extern "C" void kernel_launch(void* const* d_in, const int* in_sizes, int n_in,
                              void* d_out, int out_size)
{
    const void*  pos = d_in[0];
    const float* X   = (const float*)d_in[1];
    const float* Ws  = (const float*)d_in[2];
    const float* Bs  = (const float*)d_in[3];
    float* Out = (float*)d_out;
    (void)in_sizes; (void)n_in; (void)out_size;

    cudaFuncSetAttribute(k_main, cudaFuncAttributeMaxDynamicSharedMemorySize,
                         SMEM_BYTES);

    k_zero<<<1, 32>>>();
    k_detect<<<128, 256>>>((const unsigned int*)pos);
    k_count<<<NTOK / 256, 256>>>(pos);
    k_sched2<<<1, 544>>>();
    k_scatter<<<NTOK / 256, 256>>>(pos);
    k_prep_w<<<1152, 256>>>(Ws);
    k_main<<<NGRID, 256, SMEM_BYTES>>>(X, Bs, Out);
}

// round 12
// speedup vs baseline: 3.0804x; 1.5083x over previous
#include <cuda_runtime.h>
#include <cuda_bf16.h>
#include <cstdint>

#define NTOK   65536
#define D      128
#define NE     9
#define TILE   128
#define NGRID  521
#define XP     132          // smem X pitch in floats

// ---------------- device scratch ----------------
__device__ int g_base[NE];
__device__ int g_nsched;
__device__ int g_sched_e[NGRID + 8];
__device__ int g_sched_s[NGRID + 8];
__device__ int g_sched_n[NGRID + 8];
__device__ int g_perm[NTOK];
__device__ int g_any_odd = 0;   // reset by k_count_sched each run
__device__ int g_dtype;         // 1 = int32, 0 = int64

// W fragments pre-arranged for mma.sync B operand:
// index = (((me*9 + e)*16 + nt)*8 + ks)*32 + lane,  me = l*4+m (0..7)
// uint4 = { b0_hi, b1_hi, b0_lo, b1_lo }
#define WF_MAT_STRIDE (9 * 16 * 8 * 32)
__device__ __align__(16) uint4 g_wf[8 * WF_MAT_STRIDE];

// ---------------- helpers ----------------
__device__ __forceinline__ uint32_t pack_bf(float a, float b) {
    __nv_bfloat162 h = __floats2bfloat162_rn(a, b);
    return *(uint32_t*)&h;
}
__device__ __forceinline__ float fsig(float x) {
    return __fdividef(1.0f, 1.0f + __expf(-x));
}
__device__ __forceinline__ float ftnh(float x) {
    return __fdividef(2.0f, 1.0f + __expf(-2.0f * x)) - 1.0f;
}
__device__ __forceinline__ float gate(float x, float sf, float lg, float lf, float of) {
    float nr = x * fsig(sf) + ftnh(lg) * fsig(lf);
    return ftnh(nr) * fsig(of);
}

#define MMA(c, a, b0_, b1_)                                               \
    asm volatile(                                                         \
        "mma.sync.aligned.m16n8k16.row.col.f32.bf16.bf16.f32 "            \
        "{%0,%1,%2,%3}, {%4,%5,%6,%7}, {%8,%9}, {%0,%1,%2,%3};"           \
        : "+f"(c[0]), "+f"(c[1]), "+f"(c[2]), "+f"(c[3])                  \
        : "r"(a[0]), "r"(a[1]), "r"(a[2]), "r"(a[3]), "r"(b0_), "r"(b1_))

// ---------------- K1: dtype probe ----------------
// positions is int32[65536] (256KB) or int64[65536] (512KB). Read only the
// first 65536 32-bit words (in-bounds for both). int64 values 0..15 -> odd
// words all zero; int32 -> odd words mostly nonzero.
__global__ void k_detect(const unsigned int* __restrict__ p) {
    int i = blockIdx.x * blockDim.x + threadIdx.x;   // 0..32767
    if (i < NTOK / 2) {
        if (p[2 * i + 1] != 0u) g_any_odd = 1;       // monotone, benign race
    }
}

__device__ __forceinline__ int expert_val(long long v) {
    if (v < 0) v = 0;
    return (v < 8) ? (int)v : 8;
}

// ---------------- K2: single-block count + schedule ----------------
__global__ void k_count_sched(const void* __restrict__ pos) {
    __shared__ int s_dtype;
    __shared__ int s_cnt[NE];
    __shared__ int sbS[NE], scS[NE], tbS[NE + 1];
    const int tid = threadIdx.x;            // 1024 threads
    if (tid == 0) { s_dtype = g_any_odd; g_any_odd = 0; }
    if (tid < NE) s_cnt[tid] = 0;
    __syncthreads();
    const int dt = s_dtype;

    int c[NE];
    #pragma unroll
    for (int j = 0; j < NE; j++) c[j] = 0;
    #pragma unroll 4
    for (int t = 0; t < 64; t++) {
        int i = tid + t * 1024;
        long long v = dt ? (long long)(((const int*)pos)[i])
                         : ((const long long*)pos)[i];
        int e = expert_val(v);
        #pragma unroll
        for (int j = 0; j < NE; j++) c[j] += (e == j);
    }
    #pragma unroll
    for (int j = 0; j < NE; j++) {
        int w = __reduce_add_sync(0xffffffffu, c[j]);
        if ((tid & 31) == 0 && w) atomicAdd(&s_cnt[j], w);
    }
    __syncthreads();

    if (tid == 0) {
        g_dtype = dt;
        int off = 0, t = 0;
        for (int e = 0; e < NE; e++) {
            sbS[e] = off; scS[e] = s_cnt[e]; tbS[e] = t;
            g_base[e] = off;
            off += s_cnt[e];
            t += (s_cnt[e] + TILE - 1) / TILE;
        }
        tbS[NE] = t;
        g_nsched = t;
    }
    __syncthreads();
    int i = tid;
    if (i < tbS[NE]) {
        int e = 0;
        while (tbS[e + 1] <= i) e++;
        int k = i - tbS[e];
        g_sched_e[i] = e;
        g_sched_s[i] = sbS[e] + k * TILE;
        int rem = scS[e] - k * TILE;
        g_sched_n[i] = rem < TILE ? rem : TILE;
    }
}

// ---------------- K3: scatter + W fragment bake (fused grid) ----------------
__global__ void k_scatter_prep(const void* __restrict__ pos,
                               const float* __restrict__ Ws) {
    const int b = blockIdx.x;
    if (b < 256) {
        int i = b * 256 + threadIdx.x;
        long long v = g_dtype ? (long long)(((const int*)pos)[i])
                              : ((const long long*)pos)[i];
        int e = expert_val(v);
        int slot = atomicAdd(&g_base[e], 1);
        g_perm[slot] = i;
    } else {
        int gid = (b - 256) * 256 + threadIdx.x;   // 294912 total
        int lane = gid & 31;
        int ks   = (gid >> 5) & 7;
        int nt   = (gid >> 8) & 15;
        int rest = gid >> 12;                       // 0..71
        int e    = rest % NE;
        int me   = rest / NE;

        int k0 = ks * 16 + (lane & 3) * 2;
        int n  = nt * 8 + (lane >> 2);
        const float* Wm = Ws + ((size_t)me * NE + e) * 16384;   // [d][f]
        float w00 = Wm[(size_t)k0 * 128 + n];
        float w01 = Wm[(size_t)(k0 + 1) * 128 + n];
        float w10 = Wm[(size_t)(k0 + 8) * 128 + n];
        float w11 = Wm[(size_t)(k0 + 9) * 128 + n];

        float h00 = __bfloat162float(__float2bfloat16(w00));
        float h01 = __bfloat162float(__float2bfloat16(w01));
        float h10 = __bfloat162float(__float2bfloat16(w10));
        float h11 = __bfloat162float(__float2bfloat16(w11));

        uint4 v4;
        v4.x = pack_bf(h00, h01);
        v4.y = pack_bf(h10, h11);
        v4.z = pack_bf(w00 - h00, w01 - h01);
        v4.w = pack_bf(w10 - h10, w11 - h11);
        g_wf[gid] = v4;
    }
}

// ---------------- K4: main fused kernel ----------------
// smem: Xs[128][XP] fp32 | Alo[8 warps][8 ks][32 lanes] uint4 | bias[8][128] | idx
#define SMEM_FLOATS (128 * XP + 8192 + 1024 + 128)
#define SMEM_BYTES  (SMEM_FLOATS * 4)

extern "C" __global__ void __launch_bounds__(256, 2)
k_main(const float* __restrict__ Xg, const float* __restrict__ Bs,
       float* __restrict__ Out)
{
    int sid = blockIdx.x;
    if (sid >= g_nsched) return;
    const int e   = g_sched_e[sid];
    const int s0  = g_sched_s[sid];
    const int len = g_sched_n[sid];

    extern __shared__ float sm[];
    float* Xs   = sm;                           // 128*XP
    uint4* AloB = (uint4*)(sm + 128 * XP);      // 8*8*32 uint4
    float* sb   = sm + 128 * XP + 8192;         // 1024
    int*   sidx = (int*)(sb + 1024);            // 128

    const int tid = threadIdx.x, warp = tid >> 5, lane = tid & 31;

    if (tid < TILE) sidx[tid] = (tid < len) ? g_perm[s0 + tid] : -1;
    #pragma unroll
    for (int i = tid; i < 1024; i += 256) {
        int lm = i >> 7, f = i & 127;
        sb[i] = Bs[((size_t)lm * NE + e) * 128 + f];
    }
    __syncthreads();

    // Gather X tile (fp32) into smem
    {
        const float4* X4 = (const float4*)Xg;
        #pragma unroll 4
        for (int i = 0; i < 16; i++) {
            int el = tid + i * 256;          // 4096 float4s
            int row = el >> 5, c4 = el & 31;
            int t = sidx[row];
            float4 v = make_float4(0.f, 0.f, 0.f, 0.f);
            if (t >= 0) v = X4[(size_t)t * 32 + c4];
            *(float4*)&Xs[row * XP + c4 * 4] = v;
        }
    }
    __syncthreads();

    const int g  = lane >> 2;        // 0..7
    const int t4 = lane & 3;         // 0..3
    const int r_lo = warp * 16 + g;
    const int r_hi = r_lo + 8;
    uint4* Alo = AloB + warp * 256 + lane;   // [ks] at +ks*32

    for (int l = 0; l < 2; l++) {
        // ---- build A fragments: hi in regs, lo in smem ----
        uint32_t ahi[8][4];
        #pragma unroll
        for (int ks = 0; ks < 8; ks++) {
            int c0 = ks * 16 + t4 * 2, c8 = c0 + 8;
            float2 v00 = *(float2*)&Xs[r_lo * XP + c0];
            float2 v10 = *(float2*)&Xs[r_hi * XP + c0];
            float2 v01 = *(float2*)&Xs[r_lo * XP + c8];
            float2 v11 = *(float2*)&Xs[r_hi * XP + c8];
            float ha = __bfloat162float(__float2bfloat16(v00.x));
            float hb = __bfloat162float(__float2bfloat16(v00.y));
            uint4 lo;
            ahi[ks][0] = pack_bf(ha, hb);  lo.x = pack_bf(v00.x - ha, v00.y - hb);
            ha = __bfloat162float(__float2bfloat16(v10.x));
            hb = __bfloat162float(__float2bfloat16(v10.y));
            ahi[ks][1] = pack_bf(ha, hb);  lo.y = pack_bf(v10.x - ha, v10.y - hb);
            ha = __bfloat162float(__float2bfloat16(v01.x));
            hb = __bfloat162float(__float2bfloat16(v01.y));
            ahi[ks][2] = pack_bf(ha, hb);  lo.z = pack_bf(v01.x - ha, v01.y - hb);
            ha = __bfloat162float(__float2bfloat16(v11.x));
            hb = __bfloat162float(__float2bfloat16(v11.y));
            ahi[ks][3] = pack_bf(ha, hb);  lo.w = pack_bf(v11.x - ha, v11.y - hb);
            Alo[ks * 32] = lo;
        }

        const float* sbl = sb + l * 512;

        for (int nt = 0; nt < 16; nt++) {
            float acc[4][4];
            #pragma unroll
            for (int m = 0; m < 4; m++)
                #pragma unroll
                for (int q = 0; q < 4; q++) acc[m][q] = 0.f;

            const uint4* wp = g_wf +
                ((((size_t)(l * 4) * NE + e) * 16 + nt) * 8) * 32 + lane;

            #pragma unroll
            for (int ks = 0; ks < 8; ks++) {
                uint4 w0 = wp[0 * WF_MAT_STRIDE + ks * 32];
                uint4 w1 = wp[1 * WF_MAT_STRIDE + ks * 32];
                uint4 w2 = wp[2 * WF_MAT_STRIDE + ks * 32];
                uint4 w3 = wp[3 * WF_MAT_STRIDE + ks * 32];
                uint4 al = Alo[ks * 32];
                uint32_t alr[4] = { al.x, al.y, al.z, al.w };
                // hi * hi
                MMA(acc[0], ahi[ks], w0.x, w0.y);
                MMA(acc[1], ahi[ks], w1.x, w1.y);
                MMA(acc[2], ahi[ks], w2.x, w2.y);
                MMA(acc[3], ahi[ks], w3.x, w3.y);
                // hi * lo
                MMA(acc[0], ahi[ks], w0.z, w0.w);
                MMA(acc[1], ahi[ks], w1.z, w1.w);
                MMA(acc[2], ahi[ks], w2.z, w2.w);
                MMA(acc[3], ahi[ks], w3.z, w3.w);
                // lo * hi
                MMA(acc[0], alr, w0.x, w0.y);
                MMA(acc[1], alr, w1.x, w1.y);
                MMA(acc[2], alr, w2.x, w2.y);
                MMA(acc[3], alr, w3.x, w3.y);
            }

            // ---- epilogue for this 16x8 tile ----
            const int c0 = nt * 8 + t4 * 2;
            float2 xlo = *(float2*)&Xs[r_lo * XP + c0];
            float2 xhi = *(float2*)&Xs[r_hi * XP + c0];
            float2 b0 = *(float2*)&sbl[0 * 128 + c0];
            float2 b1 = *(float2*)&sbl[1 * 128 + c0];
            float2 b2 = *(float2*)&sbl[2 * 128 + c0];
            float2 b3 = *(float2*)&sbl[3 * 128 + c0];

            float o0 = gate(xlo.x, acc[0][0] + b0.x, acc[1][0] + b1.x,
                            acc[2][0] + b2.x, acc[3][0] + b3.x);
            float o1 = gate(xlo.y, acc[0][1] + b0.y, acc[1][1] + b1.y,
                            acc[2][1] + b2.y, acc[3][1] + b3.y);
            float o2 = gate(xhi.x, acc[0][2] + b0.x, acc[1][2] + b1.x,
                            acc[2][2] + b2.x, acc[3][2] + b3.x);
            float o3 = gate(xhi.y, acc[0][3] + b0.y, acc[1][3] + b1.y,
                            acc[2][3] + b2.y, acc[3][3] + b3.y);

            if (l == 0) {
                *(float2*)&Xs[r_lo * XP + c0] = make_float2(o0, o1);
                *(float2*)&Xs[r_hi * XP + c0] = make_float2(o2, o3);
            } else {
                int tl = sidx[r_lo];
                if (tl >= 0)
                    *(float2*)&Out[(size_t)tl * D + c0] = make_float2(o0, o1);
                int th = sidx[r_hi];
                if (th >= 0)
                    *(float2*)&Out[(size_t)th * D + c0] = make_float2(o2, o3);
            }
        }
        if (l == 0) __syncwarp();   // warp-private rows: warp sync suffices
    }
}

// ---------------- launch ----------------
extern "C" void kernel_launch(void* const* d_in, const int* in_sizes, int n_in,
                              void* d_out, int out_size)
{
    const void*  pos = d_in[0];
    const float* X   = (const float*)d_in[1];
    const float* Ws  = (const float*)d_in[2];
    const float* Bs  = (const float*)d_in[3];
    float* Out = (float*)d_out;
    (void)in_sizes; (void)n_in; (void)out_size;

    cudaFuncSetAttribute(k_main, cudaFuncAttributeMaxDynamicSharedMemorySize,
                         SMEM_BYTES);

    k_detect<<<128, 256>>>((const unsigned int*)pos);
    k_count_sched<<<1, 1024>>>(pos);
    k_scatter_prep<<<1408, 256>>>(pos, Ws);
    k_main<<<NGRID, 256, SMEM_BYTES>>>(X, Bs, Out);
}

// round 15
// speedup vs baseline: 3.5618x; 1.1563x over previous
#include <cuda_runtime.h>
#include <cuda_fp16.h>
#include <cstdint>

#define NTOK   65536
#define D      128
#define NE     9
#define TILE   128
#define NGRID  521
#define XP     132          // smem X pitch in floats

// ---------------- device scratch ----------------
__device__ int g_base[NE];
__device__ int g_nsched;
__device__ int g_sched_e[NGRID + 8];
__device__ int g_sched_s[NGRID + 8];
__device__ int g_sched_n[NGRID + 8];
__device__ int g_perm[NTOK];
__device__ int g_dtype;         // 1 = int32, 0 = int64

// W fragments pre-arranged for mma.sync B operand (fp16 hi/lo):
// index = (((me*9 + e)*16 + nt)*8 + ks)*32 + lane,  me = l*4+m (0..7)
// uint4 = { b0_hi, b1_hi, b0_lo, b1_lo }
#define WF_MAT_STRIDE (9 * 16 * 8 * 32)
__device__ __align__(16) uint4 g_wf[8 * WF_MAT_STRIDE];

// ---------------- helpers ----------------
__device__ __forceinline__ uint32_t pack_h(float a, float b) {
    __half2 h = __floats2half2_rn(a, b);
    return *(uint32_t*)&h;
}
__device__ __forceinline__ float fsig(float x) {
    return __fdividef(1.0f, 1.0f + __expf(-x));
}
__device__ __forceinline__ float ftnh(float x) {
    return __fdividef(2.0f, 1.0f + __expf(-2.0f * x)) - 1.0f;
}
__device__ __forceinline__ float gate(float x, float sf, float lg, float lf, float of) {
    float nr = x * fsig(sf) + ftnh(lg) * fsig(lf);
    return ftnh(nr) * fsig(of);
}

#define MMA(c, a, b0_, b1_)                                               \
    asm volatile(                                                         \
        "mma.sync.aligned.m16n8k16.row.col.f32.f16.f16.f32 "              \
        "{%0,%1,%2,%3}, {%4,%5,%6,%7}, {%8,%9}, {%0,%1,%2,%3};"           \
        : "+f"(c[0]), "+f"(c[1]), "+f"(c[2]), "+f"(c[3])                  \
        : "r"(a[0]), "r"(a[1]), "r"(a[2]), "r"(a[3]), "r"(b0_), "r"(b1_))

__device__ __forceinline__ int expert_val(long long v) {
    if (v < 0) v = 0;
    return (v < 8) ? (int)v : 8;
}

// ---------------- K1: dtype probe + count + schedule (one block) ----------------
// positions is int32[65536] (256KB) or int64[65536] (512KB). We read only the
// first 65536 32-bit words (in-bounds for both). int64 values 0..15 -> odd
// words all zero; int32 -> odd words mostly nonzero.
__global__ void k_count_sched(const void* __restrict__ posv) {
    __shared__ int s_cnt[NE];
    __shared__ int sbS[NE], scS[NE], tbS[NE + 1];
    const unsigned int* pw = (const unsigned int*)posv;
    const int tid = threadIdx.x;            // 1024 threads

    if (tid < NE) s_cnt[tid] = 0;

    int any = 0;
    #pragma unroll 4
    for (int t = 0; t < 32; t++)            // 32768 odd words
        any |= (pw[2 * (tid + t * 1024) + 1] != 0u);
    const int dt = __syncthreads_or(any);   // 1 = int32, 0 = int64

    int c[NE];
    #pragma unroll
    for (int j = 0; j < NE; j++) c[j] = 0;
    #pragma unroll 4
    for (int t = 0; t < 64; t++) {
        int i = tid + t * 1024;
        long long v = dt ? (long long)(((const int*)posv)[i])
                         : ((const long long*)posv)[i];
        int e = expert_val(v);
        #pragma unroll
        for (int j = 0; j < NE; j++) c[j] += (e == j);
    }
    #pragma unroll
    for (int j = 0; j < NE; j++) {
        int w = __reduce_add_sync(0xffffffffu, c[j]);
        if ((tid & 31) == 0 && w) atomicAdd(&s_cnt[j], w);
    }
    __syncthreads();

    if (tid == 0) {
        g_dtype = dt;
        int off = 0, t = 0;
        for (int e = 0; e < NE; e++) {
            sbS[e] = off; scS[e] = s_cnt[e]; tbS[e] = t;
            g_base[e] = off;
            off += s_cnt[e];
            t += (s_cnt[e] + TILE - 1) / TILE;
        }
        tbS[NE] = t;
        g_nsched = t;
    }
    __syncthreads();
    int i = tid;
    if (i < tbS[NE]) {
        int e = 0;
        while (tbS[e + 1] <= i) e++;
        int k = i - tbS[e];
        g_sched_e[i] = e;
        g_sched_s[i] = sbS[e] + k * TILE;
        int rem = scS[e] - k * TILE;
        g_sched_n[i] = rem < TILE ? rem : TILE;
    }
}

// ---------------- K2: scatter + W fragment bake (fused grid) ----------------
__global__ void k_scatter_prep(const void* __restrict__ pos,
                               const float* __restrict__ Ws) {
    const int b = blockIdx.x;
    if (b < 256) {
        int i = b * 256 + threadIdx.x;
        long long v = g_dtype ? (long long)(((const int*)pos)[i])
                              : ((const long long*)pos)[i];
        int e = expert_val(v);
        int slot = atomicAdd(&g_base[e], 1);
        g_perm[slot] = i;
    } else {
        int gid = (b - 256) * 256 + threadIdx.x;   // 294912 total
        int lane = gid & 31;
        int ks   = (gid >> 5) & 7;
        int nt   = (gid >> 8) & 15;
        int rest = gid >> 12;                       // 0..71
        int e    = rest % NE;
        int me   = rest / NE;

        int k0 = ks * 16 + (lane & 3) * 2;
        int n  = nt * 8 + (lane >> 2);
        const float* Wm = Ws + ((size_t)me * NE + e) * 16384;   // [d][f]
        float w00 = Wm[(size_t)k0 * 128 + n];
        float w01 = Wm[(size_t)(k0 + 1) * 128 + n];
        float w10 = Wm[(size_t)(k0 + 8) * 128 + n];
        float w11 = Wm[(size_t)(k0 + 9) * 128 + n];

        float h00 = __half2float(__float2half_rn(w00));
        float h01 = __half2float(__float2half_rn(w01));
        float h10 = __half2float(__float2half_rn(w10));
        float h11 = __half2float(__float2half_rn(w11));

        uint4 v4;
        v4.x = pack_h(h00, h01);
        v4.y = pack_h(h10, h11);
        v4.z = pack_h(w00 - h00, w01 - h01);
        v4.w = pack_h(w10 - h10, w11 - h11);
        g_wf[gid] = v4;
    }
}

// ---------------- K3: main fused kernel ----------------
// smem: Xs[128][XP] fp32 | bias[8][128] | idx[128]
#define SMEM_FLOATS (128 * XP + 1024 + 128)
#define SMEM_BYTES  (SMEM_FLOATS * 4)

extern "C" __global__ void __launch_bounds__(256, 2)
k_main(const float* __restrict__ Xg, const float* __restrict__ Bs,
       float* __restrict__ Out)
{
    int sid = blockIdx.x;
    if (sid >= g_nsched) return;
    const int e   = g_sched_e[sid];
    const int s0  = g_sched_s[sid];
    const int len = g_sched_n[sid];

    extern __shared__ float sm[];
    float* Xs   = sm;                           // 128*XP
    float* sb   = sm + 128 * XP;                // 1024
    int*   sidx = (int*)(sb + 1024);            // 128

    const int tid = threadIdx.x, warp = tid >> 5, lane = tid & 31;

    if (tid < TILE) sidx[tid] = (tid < len) ? g_perm[s0 + tid] : -1;
    #pragma unroll
    for (int i = tid; i < 1024; i += 256) {
        int lm = i >> 7, f = i & 127;
        sb[i] = Bs[((size_t)lm * NE + e) * 128 + f];
    }
    __syncthreads();

    // Gather X tile (fp32) into smem
    {
        const float4* X4 = (const float4*)Xg;
        #pragma unroll 4
        for (int i = 0; i < 16; i++) {
            int el = tid + i * 256;          // 4096 float4s
            int row = el >> 5, c4 = el & 31;
            int t = sidx[row];
            float4 v = make_float4(0.f, 0.f, 0.f, 0.f);
            if (t >= 0) v = X4[(size_t)t * 32 + c4];
            *(float4*)&Xs[row * XP + c4 * 4] = v;
        }
    }
    __syncthreads();

    const int g  = lane >> 2;        // 0..7
    const int t4 = lane & 3;         // 0..3
    const int r_lo = warp * 16 + g;
    const int r_hi = r_lo + 8;

    for (int l = 0; l < 2; l++) {
        // ---- build fp16 A fragments for this warp's 16 rows, K=128 ----
        uint32_t ah[8][4];
        #pragma unroll
        for (int ks = 0; ks < 8; ks++) {
            int c0 = ks * 16 + t4 * 2, c8 = c0 + 8;
            float2 v00 = *(float2*)&Xs[r_lo * XP + c0];
            float2 v10 = *(float2*)&Xs[r_hi * XP + c0];
            float2 v01 = *(float2*)&Xs[r_lo * XP + c8];
            float2 v11 = *(float2*)&Xs[r_hi * XP + c8];
            ah[ks][0] = pack_h(v00.x, v00.y);
            ah[ks][1] = pack_h(v10.x, v10.y);
            ah[ks][2] = pack_h(v01.x, v01.y);
            ah[ks][3] = pack_h(v11.x, v11.y);
        }

        const float* sbl = sb + l * 512;

        for (int nt = 0; nt < 16; nt++) {
            float acc[4][4];
            #pragma unroll
            for (int m = 0; m < 4; m++)
                #pragma unroll
                for (int q = 0; q < 4; q++) acc[m][q] = 0.f;

            const uint4* wp = g_wf +
                ((((size_t)(l * 4) * NE + e) * 16 + nt) * 8) * 32 + lane;

            #pragma unroll
            for (int ks = 0; ks < 8; ks++) {
                uint4 w0 = wp[0 * WF_MAT_STRIDE + ks * 32];
                uint4 w1 = wp[1 * WF_MAT_STRIDE + ks * 32];
                uint4 w2 = wp[2 * WF_MAT_STRIDE + ks * 32];
                uint4 w3 = wp[3 * WF_MAT_STRIDE + ks * 32];
                // x_h * w_hi
                MMA(acc[0], ah[ks], w0.x, w0.y);
                MMA(acc[1], ah[ks], w1.x, w1.y);
                MMA(acc[2], ah[ks], w2.x, w2.y);
                MMA(acc[3], ah[ks], w3.x, w3.y);
                // x_h * w_lo
                MMA(acc[0], ah[ks], w0.z, w0.w);
                MMA(acc[1], ah[ks], w1.z, w1.w);
                MMA(acc[2], ah[ks], w2.z, w2.w);
                MMA(acc[3], ah[ks], w3.z, w3.w);
            }

            // ---- epilogue for this 16x8 tile ----
            const int c0 = nt * 8 + t4 * 2;
            float2 xlo = *(float2*)&Xs[r_lo * XP + c0];
            float2 xhi = *(float2*)&Xs[r_hi * XP + c0];
            float2 b0 = *(float2*)&sbl[0 * 128 + c0];
            float2 b1 = *(float2*)&sbl[1 * 128 + c0];
            float2 b2 = *(float2*)&sbl[2 * 128 + c0];
            float2 b3 = *(float2*)&sbl[3 * 128 + c0];

            float o0 = gate(xlo.x, acc[0][0] + b0.x, acc[1][0] + b1.x,
                            acc[2][0] + b2.x, acc[3][0] + b3.x);
            float o1 = gate(xlo.y, acc[0][1] + b0.y, acc[1][1] + b1.y,
                            acc[2][1] + b2.y, acc[3][1] + b3.y);
            float o2 = gate(xhi.x, acc[0][2] + b0.x, acc[1][2] + b1.x,
                            acc[2][2] + b2.x, acc[3][2] + b3.x);
            float o3 = gate(xhi.y, acc[0][3] + b0.y, acc[1][3] + b1.y,
                            acc[2][3] + b2.y, acc[3][3] + b3.y);

            if (l == 0) {
                *(float2*)&Xs[r_lo * XP + c0] = make_float2(o0, o1);
                *(float2*)&Xs[r_hi * XP + c0] = make_float2(o2, o3);
            } else {
                int tl = sidx[r_lo];
                if (tl >= 0)
                    *(float2*)&Out[(size_t)tl * D + c0] = make_float2(o0, o1);
                int th = sidx[r_hi];
                if (th >= 0)
                    *(float2*)&Out[(size_t)th * D + c0] = make_float2(o2, o3);
            }
        }
        if (l == 0) __syncwarp();   // warp-private rows: warp sync suffices
    }
}

// ---------------- launch ----------------
extern "C" void kernel_launch(void* const* d_in, const int* in_sizes, int n_in,
                              void* d_out, int out_size)
{
    const void*  pos = d_in[0];
    const float* X   = (const float*)d_in[1];
    const float* Ws  = (const float*)d_in[2];
    const float* Bs  = (const float*)d_in[3];
    float* Out = (float*)d_out;
    (void)in_sizes; (void)n_in; (void)out_size;

    cudaFuncSetAttribute(k_main, cudaFuncAttributeMaxDynamicSharedMemorySize,
                         SMEM_BYTES);

    k_count_sched<<<1, 1024>>>(pos);
    k_scatter_prep<<<1408, 256>>>(pos, Ws);
    k_main<<<NGRID, 256, SMEM_BYTES>>>(X, Bs, Out);
}

// round 16
// speedup vs baseline: 4.5113x; 1.2666x over previous
#include <cuda_runtime.h>
#include <cuda_fp16.h>
#include <cstdint>

#define NTOK   65536
#define D      128
#define NE     9
#define TILE   128
#define NGRID  521
#define XP     132          // smem X pitch in floats
#define PGRID  304          // persistent grid: 152 SMs x 2 CTAs

// ---------------- device scratch ----------------
__device__ int g_cnt[NE];         // zero-init; finalizer re-zeros each run
__device__ int g_ticket = 0;      // finalizer resets
__device__ int g_base[NE];
__device__ int g_nsched;
__device__ int g_sched_e[NGRID + 8];
__device__ int g_sched_s[NGRID + 8];
__device__ int g_sched_n[NGRID + 8];
__device__ int g_perm[NTOK];
__device__ int g_dtype;           // 1 = int32, 0 = int64

// W fragments pre-arranged for mma.sync B operand (fp16 hi/lo):
// index = (((me*9 + e)*16 + nt)*8 + ks)*32 + lane,  me = l*4+m (0..7)
// uint4 = { b0_hi, b1_hi, b0_lo, b1_lo }
#define WF_MAT_STRIDE (9 * 16 * 8 * 32)
__device__ __align__(16) uint4 g_wf[8 * WF_MAT_STRIDE];

// ---------------- helpers ----------------
__device__ __forceinline__ uint32_t pack_h(float a, float b) {
    __half2 h = __floats2half2_rn(a, b);
    return *(uint32_t*)&h;
}
__device__ __forceinline__ float fsig(float x) {
    return __fdividef(1.0f, 1.0f + __expf(-x));
}
__device__ __forceinline__ float ftnh(float x) {
    return __fdividef(2.0f, 1.0f + __expf(-2.0f * x)) - 1.0f;
}
__device__ __forceinline__ float gate(float x, float sf, float lg, float lf, float of) {
    float nr = x * fsig(sf) + ftnh(lg) * fsig(lf);
    return ftnh(nr) * fsig(of);
}

#define MMA(c, a, b0_, b1_)                                               \
    asm volatile(                                                         \
        "mma.sync.aligned.m16n8k16.row.col.f32.f16.f16.f32 "              \
        "{%0,%1,%2,%3}, {%4,%5,%6,%7}, {%8,%9}, {%0,%1,%2,%3};"           \
        : "+f"(c[0]), "+f"(c[1]), "+f"(c[2]), "+f"(c[3])                  \
        : "r"(a[0]), "r"(a[1]), "r"(a[2]), "r"(a[3]), "r"(b0_), "r"(b1_))

__device__ __forceinline__ int expert_val(long long v) {
    if (v < 0) v = 0;
    return (v < 8) ? (int)v : 8;
}

// ---------------- K1: parallel count + last-block schedule ----------------
// Dtype probe is per-block: block b reads the 128 odd 32-bit words of tokens
// [b*128, (b+1)*128) — inside the first 256KB, in-bounds for both dtypes.
// int64 (values 0..15): odd words all zero. int32: P(128 random [0,16) words
// all zero) = 16^-128 ~= 0. So each block decides dtype independently+consistently.
__global__ void k_count(const void* __restrict__ posv) {
    __shared__ int s_cnt[NE];
    __shared__ int s_fin;
    const unsigned int* pw = (const unsigned int*)posv;
    const int tid = threadIdx.x;               // 256 threads
    const int b   = blockIdx.x;                // 256 blocks

    if (tid < NE) s_cnt[tid] = 0;

    int any = 0;
    if (tid < 128) any = (pw[2 * (b * 128 + tid) + 1] != 0u);
    const int dt = __syncthreads_or(any);      // 1 = int32, 0 = int64

    const int i = b * 256 + tid;
    long long v = dt ? (long long)(((const int*)posv)[i])
                     : ((const long long*)posv)[i];
    const int e = expert_val(v);
    atomicAdd(&s_cnt[e], 1);
    __syncthreads();
    if (tid < NE && s_cnt[tid]) atomicAdd(&g_cnt[tid], s_cnt[tid]);
    if (tid == 0 && b == 0) g_dtype = dt;

    // last block finalizes: bases + tile schedule, then resets scratch
    __threadfence();
    if (tid == 0) s_fin = (atomicAdd(&g_ticket, 1) == gridDim.x - 1);
    __syncthreads();
    if (!s_fin) return;

    __shared__ int sbS[NE], scS[NE], tbS[NE + 1];
    if (tid == 0) {
        int off = 0, t = 0;
        for (int e2 = 0; e2 < NE; e2++) {
            sbS[e2] = off; scS[e2] = g_cnt[e2]; tbS[e2] = t;
            g_base[e2] = off;
            off += scS[e2];
            t += (scS[e2] + TILE - 1) / TILE;
        }
        tbS[NE] = t;
        g_nsched = t;
        g_ticket = 0;                          // reset for next graph replay
    }
    if (tid < NE) g_cnt[tid] = 0;              // reset for next graph replay
    __syncthreads();
    for (int i2 = tid; i2 < tbS[NE]; i2 += 256) {
        int e2 = 0;
        while (tbS[e2 + 1] <= i2) e2++;
        int k = i2 - tbS[e2];
        g_sched_e[i2] = e2;
        g_sched_s[i2] = sbS[e2] + k * TILE;
        int rem = scS[e2] - k * TILE;
        g_sched_n[i2] = rem < TILE ? rem : TILE;
    }
}

// ---------------- K2: scatter (block-aggregated) + W fragment bake ----------------
__global__ void k_scatter_prep(const void* __restrict__ pos,
                               const float* __restrict__ Ws) {
    const int b = blockIdx.x;
    if (b < 256) {
        __shared__ int s_cnt[NE], s_base[NE];
        const int tid = threadIdx.x;
        if (tid < NE) s_cnt[tid] = 0;
        __syncthreads();
        const int i = b * 256 + tid;
        long long v = g_dtype ? (long long)(((const int*)pos)[i])
                              : ((const long long*)pos)[i];
        const int e = expert_val(v);
        const int rank = atomicAdd(&s_cnt[e], 1);
        __syncthreads();
        if (tid < NE && s_cnt[tid]) s_base[tid] = atomicAdd(&g_base[tid], s_cnt[tid]);
        __syncthreads();
        g_perm[s_base[e] + rank] = i;
    } else {
        int gid = (b - 256) * 256 + threadIdx.x;   // 294912 total
        int lane = gid & 31;
        int ks   = (gid >> 5) & 7;
        int nt   = (gid >> 8) & 15;
        int rest = gid >> 12;                       // 0..71
        int e    = rest % NE;
        int me   = rest / NE;

        int k0 = ks * 16 + (lane & 3) * 2;
        int n  = nt * 8 + (lane >> 2);
        const float* Wm = Ws + ((size_t)me * NE + e) * 16384;   // [d][f]
        float w00 = Wm[(size_t)k0 * 128 + n];
        float w01 = Wm[(size_t)(k0 + 1) * 128 + n];
        float w10 = Wm[(size_t)(k0 + 8) * 128 + n];
        float w11 = Wm[(size_t)(k0 + 9) * 128 + n];

        float h00 = __half2float(__float2half_rn(w00));
        float h01 = __half2float(__float2half_rn(w01));
        float h10 = __half2float(__float2half_rn(w10));
        float h11 = __half2float(__float2half_rn(w11));

        uint4 v4;
        v4.x = pack_h(h00, h01);
        v4.y = pack_h(h10, h11);
        v4.z = pack_h(w00 - h00, w01 - h01);
        v4.w = pack_h(w10 - h10, w11 - h11);
        g_wf[gid] = v4;
    }
}

// ---------------- K3: persistent main fused kernel ----------------
// smem: Xs[128][XP] fp32 | bias[8][128] | idx[128]
#define SMEM_FLOATS (128 * XP + 1024 + 128)
#define SMEM_BYTES  (SMEM_FLOATS * 4)

extern "C" __global__ void __launch_bounds__(256, 2)
k_main(const float* __restrict__ Xg, const float* __restrict__ Bs,
       float* __restrict__ Out)
{
    extern __shared__ float sm[];
    float* Xs   = sm;                           // 128*XP
    float* sb   = sm + 128 * XP;                // 1024
    int*   sidx = (int*)(sb + 1024);            // 128

    const int tid = threadIdx.x, warp = tid >> 5, lane = tid & 31;
    const int g  = lane >> 2;        // 0..7
    const int t4 = lane & 3;         // 0..3
    const int r_lo = warp * 16 + g;
    const int r_hi = r_lo + 8;
    const int nsched = g_nsched;

    for (int sid = blockIdx.x; sid < nsched; sid += PGRID) {
        const int e   = g_sched_e[sid];
        const int s0  = g_sched_s[sid];
        const int len = g_sched_n[sid];

        __syncthreads();   // protect smem reuse across persistent iterations

        if (tid < TILE) sidx[tid] = (tid < len) ? g_perm[s0 + tid] : -1;
        #pragma unroll
        for (int i = tid; i < 1024; i += 256) {
            int lm = i >> 7, f = i & 127;
            sb[i] = Bs[((size_t)lm * NE + e) * 128 + f];
        }
        __syncthreads();

        // Gather X tile (fp32) into smem
        {
            const float4* X4 = (const float4*)Xg;
            #pragma unroll 4
            for (int i = 0; i < 16; i++) {
                int el = tid + i * 256;          // 4096 float4s
                int row = el >> 5, c4 = el & 31;
                int t = sidx[row];
                float4 v = make_float4(0.f, 0.f, 0.f, 0.f);
                if (t >= 0) v = X4[(size_t)t * 32 + c4];
                *(float4*)&Xs[row * XP + c4 * 4] = v;
            }
        }
        __syncthreads();

        for (int l = 0; l < 2; l++) {
            // ---- build fp16 A fragments for this warp's 16 rows, K=128 ----
            uint32_t ah[8][4];
            #pragma unroll
            for (int ks = 0; ks < 8; ks++) {
                int c0 = ks * 16 + t4 * 2, c8 = c0 + 8;
                float2 v00 = *(float2*)&Xs[r_lo * XP + c0];
                float2 v10 = *(float2*)&Xs[r_hi * XP + c0];
                float2 v01 = *(float2*)&Xs[r_lo * XP + c8];
                float2 v11 = *(float2*)&Xs[r_hi * XP + c8];
                ah[ks][0] = pack_h(v00.x, v00.y);
                ah[ks][1] = pack_h(v10.x, v10.y);
                ah[ks][2] = pack_h(v01.x, v01.y);
                ah[ks][3] = pack_h(v11.x, v11.y);
            }

            const float* sbl = sb + l * 512;

            for (int nt = 0; nt < 16; nt++) {
                float acc[4][4];
                #pragma unroll
                for (int m = 0; m < 4; m++)
                    #pragma unroll
                    for (int q = 0; q < 4; q++) acc[m][q] = 0.f;

                const uint4* wp = g_wf +
                    ((((size_t)(l * 4) * NE + e) * 16 + nt) * 8) * 32 + lane;

                #pragma unroll
                for (int ks = 0; ks < 8; ks++) {
                    uint4 w0 = wp[0 * WF_MAT_STRIDE + ks * 32];
                    uint4 w1 = wp[1 * WF_MAT_STRIDE + ks * 32];
                    uint4 w2 = wp[2 * WF_MAT_STRIDE + ks * 32];
                    uint4 w3 = wp[3 * WF_MAT_STRIDE + ks * 32];
                    // x_h * w_hi
                    MMA(acc[0], ah[ks], w0.x, w0.y);
                    MMA(acc[1], ah[ks], w1.x, w1.y);
                    MMA(acc[2], ah[ks], w2.x, w2.y);
                    MMA(acc[3], ah[ks], w3.x, w3.y);
                    // x_h * w_lo
                    MMA(acc[0], ah[ks], w0.z, w0.w);
                    MMA(acc[1], ah[ks], w1.z, w1.w);
                    MMA(acc[2], ah[ks], w2.z, w2.w);
                    MMA(acc[3], ah[ks], w3.z, w3.w);
                }

                // ---- epilogue for this 16x8 tile ----
                const int c0 = nt * 8 + t4 * 2;
                float2 xlo = *(float2*)&Xs[r_lo * XP + c0];
                float2 xhi = *(float2*)&Xs[r_hi * XP + c0];
                float2 b0 = *(float2*)&sbl[0 * 128 + c0];
                float2 b1 = *(float2*)&sbl[1 * 128 + c0];
                float2 b2 = *(float2*)&sbl[2 * 128 + c0];
                float2 b3 = *(float2*)&sbl[3 * 128 + c0];

                float o0 = gate(xlo.x, acc[0][0] + b0.x, acc[1][0] + b1.x,
                                acc[2][0] + b2.x, acc[3][0] + b3.x);
                float o1 = gate(xlo.y, acc[0][1] + b0.y, acc[1][1] + b1.y,
                                acc[2][1] + b2.y, acc[3][1] + b3.y);
                float o2 = gate(xhi.x, acc[0][2] + b0.x, acc[1][2] + b1.x,
                                acc[2][2] + b2.x, acc[3][2] + b3.x);
                float o3 = gate(xhi.y, acc[0][3] + b0.y, acc[1][3] + b1.y,
                                acc[2][3] + b2.y, acc[3][3] + b3.y);

                if (l == 0) {
                    *(float2*)&Xs[r_lo * XP + c0] = make_float2(o0, o1);
                    *(float2*)&Xs[r_hi * XP + c0] = make_float2(o2, o3);
                } else {
                    int tl = sidx[r_lo];
                    if (tl >= 0)
                        *(float2*)&Out[(size_t)tl * D + c0] = make_float2(o0, o1);
                    int th = sidx[r_hi];
                    if (th >= 0)
                        *(float2*)&Out[(size_t)th * D + c0] = make_float2(o2, o3);
                }
            }
            if (l == 0) __syncwarp();   // warp-private rows: warp sync suffices
        }
    }
}

// ---------------- launch ----------------
extern "C" void kernel_launch(void* const* d_in, const int* in_sizes, int n_in,
                              void* d_out, int out_size)
{
    const void*  pos = d_in[0];
    const float* X   = (const float*)d_in[1];
    const float* Ws  = (const float*)d_in[2];
    const float* Bs  = (const float*)d_in[3];
    float* Out = (float*)d_out;
    (void)in_sizes; (void)n_in; (void)out_size;

    cudaFuncSetAttribute(k_main, cudaFuncAttributeMaxDynamicSharedMemorySize,
                         SMEM_BYTES);

    k_count<<<256, 256>>>(pos);
    k_scatter_prep<<<1408, 256>>>(pos, Ws);
    k_main<<<PGRID, 256, SMEM_BYTES>>>(X, Bs, Out);
}